// round 12
// baseline (speedup 1.0000x reference)
#include <cuda_runtime.h>
#include <cuda_fp16.h>
#include <cstdint>
#include <math.h>
#include <float.h>

#define Lq 512
#define Bq 8
#define Nq 32
#define Dq 256
#define GHq 128
#define AHq 64
#define KC 512
#define THREADS 256

// fp16 weights, [n][k] k-contiguous
__device__ __half g_w1h[GHq * KC];     // [128][512]
__device__ __half g_w2h[AHq * Dq];     // [64][256]
__device__ int g_mask_mode;            // 0 = byte bool, 1 = int32, 2 = float32

__global__ void prep_kernel(const float* __restrict__ gw1, const float* __restrict__ aw1,
                            const unsigned char* __restrict__ mask_raw) {
    int i = blockIdx.x * blockDim.x + threadIdx.x;
    if (i < GHq * KC) g_w1h[i] = __float2half_rn(gw1[i]);
    if (i < AHq * Dq) g_w2h[i] = __float2half_rn(aw1[i]);
    // parallel mask-dtype sniffer (block 0): float32 1.0f = {00,00,80,3F};
    // int32 0/1 has zero bytes at j%4!=0; byte-bool has 0/1 bytes everywhere.
    if (blockIdx.x == 0) {
        __shared__ int s_flags[2];
        if (threadIdx.x == 0) { s_flags[0] = 0; s_flags[1] = 0; }
        __syncthreads();
        bool fsig = false, onz = false;
        for (int j = threadIdx.x; j < 4096; j += THREADS) {
            unsigned char c = mask_raw[j];
            if (j & 3) {
                if (c == 0x3Fu || c == 0x80u) fsig = true;
                if (c != 0) onz = true;
            }
        }
        if (__any_sync(0xffffffffu, fsig) && (threadIdx.x & 31) == 0) atomicOr(&s_flags[0], 1);
        if (__any_sync(0xffffffffu, onz) && (threadIdx.x & 31) == 0) atomicOr(&s_flags[1], 1);
        __syncthreads();
        if (threadIdx.x == 0)
            g_mask_mode = s_flags[0] ? 2 : (s_flags[1] ? 0 : 1);
    }
}

__device__ __forceinline__ uint32_t smem_u32(const void* p) {
    return (uint32_t)__cvta_generic_to_shared(p);
}
__device__ __forceinline__ void ldmatrix_x4(uint32_t* r, uint32_t addr) {
    asm volatile("ldmatrix.sync.aligned.m8n8.x4.shared.b16 {%0,%1,%2,%3}, [%4];"
                 : "=r"(r[0]), "=r"(r[1]), "=r"(r[2]), "=r"(r[3]) : "r"(addr));
}
__device__ __forceinline__ void mma16816(float* c, const uint32_t* a, uint32_t b0, uint32_t b1) {
    asm volatile("mma.sync.aligned.m16n8k16.row.col.f32.f16.f16.f32 "
                 "{%0,%1,%2,%3},{%4,%5,%6,%7},{%8,%9},{%0,%1,%2,%3};"
                 : "+f"(c[0]), "+f"(c[1]), "+f"(c[2]), "+f"(c[3])
                 : "r"(a[0]), "r"(a[1]), "r"(a[2]), "r"(a[3]), "r"(b0), "r"(b1));
}
__device__ __forceinline__ void cp16(uint32_t dst, const void* src) {
    asm volatile("cp.async.cg.shared.global [%0], [%1], 16;" :: "r"(dst), "l"(src));
}
__device__ __forceinline__ void cp_commit() { asm volatile("cp.async.commit_group;"); }
__device__ __forceinline__ void cp_wait0() { asm volatile("cp.async.wait_group 0;" ::: "memory"); }

// SMEM layout (bytes); stride 72 halves = 144 B rows (16B-aligned, conflict-free ldmatrix)
#define A_STRIDE 72
#define OFF_A16 0                       // [64][72] fp16 = 9216
#define OFF_W1 9216                     // [128][72] fp16 = 18432
#define OFF_W2 27648                    // [64][72] fp16 = 9216
#define OFF_GPART 36864                 // float [64][4]
#define OFF_GATE (OFF_GPART + 1024)     // float [64]
#define OFF_ATTN (OFF_GATE + 256)       // float [64]
#define SMEM_TOTAL (OFF_ATTN + 256 + 64)

__global__ __launch_bounds__(THREADS, 3)
void fusion_main(const float* __restrict__ vert, const float* __restrict__ horiz,
                 const unsigned char* __restrict__ mask,
                 const float* __restrict__ gb1, const float* __restrict__ gw2,
                 const float* __restrict__ gb2,
                 const float* __restrict__ ab1, const float* __restrict__ aw2,
                 const float* __restrict__ ab2,
                 float* __restrict__ out_fused, float* __restrict__ out_pm,
                 float* __restrict__ out_attn) {
    extern __shared__ char smem[];
    __half* A16 = (__half*)(smem + OFF_A16);
    float* gpart = (float*)(smem + OFF_GPART);
    float* gate_s = (float*)(smem + OFF_GATE);
    float* attn_s = (float*)(smem + OFF_ATTN);

    const int tid = threadIdx.x;
    const int wid = tid >> 5;
    const int lane = tid & 31;
    const int cta = blockIdx.x;          // 2 lb pairs: lb = cta*2 + lbi
    const uint32_t sbase = smem_u32(smem);

    const int mg = wid >> 2;             // warp grid 2m x 4n
    const int ng = wid & 3;

    const int lgrp = lane >> 3;
    const int lrow = (lane & 7) + (lgrp & 1) * 8;
    const int lcol = (lgrp >> 1) * 8;
    const int bn_off = ((lane >> 4) & 1) * 8 + (lane & 7);
    const int bk_off = ((lane >> 3) & 1) * 8;

    // ========== GEMM1 + fused GEMM2 (Yv/Yh) over 8 k64 chunks ==========
    float acc1[2][4][4];
    float accv[2][2][4], acch[2][2][4];
#pragma unroll
    for (int a = 0; a < 2; a++) {
#pragma unroll
        for (int b = 0; b < 4; b++)
#pragma unroll
            for (int c = 0; c < 4; c++) acc1[a][b][c] = 0.f;
#pragma unroll
        for (int b = 0; b < 2; b++)
#pragma unroll
            for (int c = 0; c < 4; c++) { accv[a][b][c] = 0.f; acch[a][b][c] = 0.f; }
    }

#pragma unroll 1
    for (int chunk = 0; chunk < 8; chunk++) {
        const float* feat = (chunk < 4) ? vert : horiz;
        const int kb = (chunk & 3) * 64;
        __syncthreads();                 // buffers reusable (mma(chunk-1) done)
        // W1 + W2 chunk via cp.async (flies under the A LDG+convert below)
#pragma unroll
        for (int t = 0; t < 4; t++) {
            int j = tid + t * THREADS;   // 128 n x 8 q
            int n = j >> 3;
            int q = j & 7;
            cp16(sbase + OFF_W1 + n * 144 + q * 16,
                 g_w1h + n * KC + chunk * 64 + q * 8);
        }
#pragma unroll
        for (int t = 0; t < 2; t++) {
            int j = tid + t * THREADS;   // 64 n x 8 q
            int n = j >> 3;
            int q = j & 7;
            cp16(sbase + OFF_W2 + n * 144 + q * 16,
                 g_w2h + n * Dq + kb + q * 8);
        }
        cp_commit();
        // stage A chunk: 64 m x 64 k fp32 -> fp16
        {
            const float4* src = (const float4*)(feat + (size_t)cta * 64 * Dq);
#pragma unroll
            for (int t = 0; t < 4; t++) {
                int j = tid + t * THREADS;   // 0..1023
                int m = j >> 4;
                int kq = (j & 15) * 4;
                float4 v = src[m * (Dq / 4) + (kb + kq) / 4];
                __half2 h01 = __floats2half2_rn(v.x, v.y);
                __half2 h23 = __floats2half2_rn(v.z, v.w);
                *(uint2*)&A16[m * A_STRIDE + kq] =
                    make_uint2(*(uint32_t*)&h01, *(uint32_t*)&h23);
            }
        }
        cp_wait0();
        __syncthreads();

#pragma unroll
        for (int ks = 0; ks < 4; ks++) {
            const int kk = ks * 16;
            uint32_t a[2][4];
#pragma unroll
            for (int mt = 0; mt < 2; mt++) {
                int row = mg * 32 + mt * 16 + lrow;
                ldmatrix_x4(a[mt], sbase + OFF_A16 + row * 144 + (kk + lcol) * 2);
            }
            // GEMM1
#pragma unroll
            for (int nh = 0; nh < 2; nh++) {
                uint32_t b[4];
                ldmatrix_x4(b, sbase + OFF_W1 +
                               (ng * 32 + nh * 16 + bn_off) * 144 + (kk + bk_off) * 2);
#pragma unroll
                for (int nf2 = 0; nf2 < 2; nf2++) {
                    int nf = nh * 2 + nf2;
#pragma unroll
                    for (int mt = 0; mt < 2; mt++)
                        mma16816(acc1[mt][nf], a[mt], b[nf2 * 2], b[nf2 * 2 + 1]);
                }
            }
            // fused GEMM2 (A frags reused)
            {
                uint32_t b2[4];
                ldmatrix_x4(b2, sbase + OFF_W2 +
                                (ng * 16 + bn_off) * 144 + (kk + bk_off) * 2);
                if (chunk < 4) {
#pragma unroll
                    for (int nf = 0; nf < 2; nf++)
#pragma unroll
                        for (int mt = 0; mt < 2; mt++)
                            mma16816(accv[mt][nf], a[mt], b2[nf * 2], b2[nf * 2 + 1]);
                } else {
#pragma unroll
                    for (int nf = 0; nf < 2; nf++)
#pragma unroll
                        for (int mt = 0; mt < 2; mt++)
                            mma16816(acch[mt][nf], a[mt], b2[nf * 2], b2[nf * 2 + 1]);
                }
            }
        }
    }

    // ---- gate epilogue: relu(C1+gb1) . gw2 -> sigmoid ----
    {
        float p0[2] = {0.f, 0.f}, p1[2] = {0.f, 0.f};
#pragma unroll
        for (int nf = 0; nf < 4; nf++) {
#pragma unroll
            for (int j = 0; j < 2; j++) {
                int n = ng * 32 + nf * 8 + 2 * (lane & 3) + j;
                float b1v = __ldg(&gb1[n]);
                float w2v = __ldg(&gw2[n]);
#pragma unroll
                for (int mt = 0; mt < 2; mt++) {
                    p0[mt] += fmaxf(acc1[mt][nf][j] + b1v, 0.f) * w2v;
                    p1[mt] += fmaxf(acc1[mt][nf][j + 2] + b1v, 0.f) * w2v;
                }
            }
        }
#pragma unroll
        for (int o = 1; o <= 2; o <<= 1) {
#pragma unroll
            for (int mt = 0; mt < 2; mt++) {
                p0[mt] += __shfl_xor_sync(0xffffffffu, p0[mt], o);
                p1[mt] += __shfl_xor_sync(0xffffffffu, p1[mt], o);
            }
        }
        if ((lane & 3) == 0) {
            int r = lane >> 2;
#pragma unroll
            for (int mt = 0; mt < 2; mt++) {
                gpart[(mg * 32 + mt * 16 + r) * 4 + ng] = p0[mt];
                gpart[(mg * 32 + mt * 16 + 8 + r) * 4 + ng] = p1[mt];
            }
        }
        __syncthreads();
        if (tid < 64) {
            float s = gpart[tid * 4] + gpart[tid * 4 + 1] + gpart[tid * 4 + 2] + gpart[tid * 4 + 3];
            s += __ldg(gb2);
            gate_s[tid] = 1.f / (1.f + __expf(-s));
        }
        __syncthreads();
    }

    // ---- logits epilogue: tanh(g*Yv + (1-g)*Yh + ab1) . aw2 ----
    {
        float p0[2] = {0.f, 0.f}, p1[2] = {0.f, 0.f};
        int r = lane >> 2;
        float gA[2], gB[2];
#pragma unroll
        for (int mt = 0; mt < 2; mt++) {
            gA[mt] = gate_s[mg * 32 + mt * 16 + r];
            gB[mt] = gate_s[mg * 32 + mt * 16 + 8 + r];
        }
#pragma unroll
        for (int nf = 0; nf < 2; nf++) {
#pragma unroll
            for (int j = 0; j < 2; j++) {
                int n = ng * 16 + nf * 8 + 2 * (lane & 3) + j;
                float b1v = __ldg(&ab1[n]);
                float w2v = __ldg(&aw2[n]);
#pragma unroll
                for (int mt = 0; mt < 2; mt++) {
                    float pre0 = fmaf(gA[mt], accv[mt][nf][j] - acch[mt][nf][j], acch[mt][nf][j]) + b1v;
                    p0[mt] += tanhf(pre0) * w2v;
                    float pre1 = fmaf(gB[mt], accv[mt][nf][j + 2] - acch[mt][nf][j + 2], acch[mt][nf][j + 2]) + b1v;
                    p1[mt] += tanhf(pre1) * w2v;
                }
            }
        }
#pragma unroll
        for (int o = 1; o <= 2; o <<= 1) {
#pragma unroll
            for (int mt = 0; mt < 2; mt++) {
                p0[mt] += __shfl_xor_sync(0xffffffffu, p0[mt], o);
                p1[mt] += __shfl_xor_sync(0xffffffffu, p1[mt], o);
            }
        }
        if ((lane & 3) == 0) {
#pragma unroll
            for (int mt = 0; mt < 2; mt++) {
                gpart[(mg * 32 + mt * 16 + r) * 4 + ng] = p0[mt];
                gpart[(mg * 32 + mt * 16 + 8 + r) * 4 + ng] = p1[mt];
            }
        }
        __syncthreads();
    }

    // ---- masked softmax per lb (2 warps; lane = msg) ----
    if (tid < 64) {
        int lbi = tid >> 5;
        int msg = tid & 31;
        int lb = cta * 2 + lbi;
        int l = lb >> 3, b = lb & 7;
        float lg = gpart[tid * 4] + gpart[tid * 4 + 1] + gpart[tid * 4 + 2] + gpart[tid * 4 + 3];
        lg += __ldg(ab2);
        size_t midx = ((size_t)b * Nq + msg) * Lq + l;
        int mode = g_mask_mode;
        bool valid;
        if (mode == 2)      valid = ((const float*)mask)[midx] != 0.0f;
        else if (mode == 1) valid = ((const int*)mask)[midx] != 0;
        else                valid = mask[midx] != 0;
        float mv = valid ? lg : -FLT_MAX;
#pragma unroll
        for (int o = 16; o >= 1; o >>= 1)
            mv = fmaxf(mv, __shfl_xor_sync(0xffffffffu, mv, o));
        float e = valid ? __expf(lg - mv) : 0.f;
        float s = e;
#pragma unroll
        for (int o = 16; o >= 1; o >>= 1)
            s += __shfl_xor_sync(0xffffffffu, s, o);
        float a = (s > 0.f) ? e / s : 0.f;
        attn_s[tid] = a;
        out_attn[((size_t)b * Lq + l) * Nq + msg] = a;
    }
    __syncthreads();

    // ---- blend + fused in one pass (exact fp32 from gmem): p = g*(v-h)+h ----
#pragma unroll 1
    for (int it = 0; it < 2; it++) {
        int idx = tid + it * THREADS;    // 0..511 = 2 lb x 256 d
        int lbi = idx >> 8;
        int d = idx & 255;
        size_t base = (size_t)(cta * 64 + lbi * 32) * Dq + d;
        const float* vb = vert + base;
        const float* hb = horiz + base;
        float* pmb = out_pm + base;
        float f = 0.f;
#pragma unroll
        for (int m = 0; m < Nq; m++) {
            float g = gate_s[lbi * 32 + m];
            float v = vb[m * Dq];
            float h = hb[m * Dq];
            float p = fmaf(g, v - h, h);
            pmb[m * Dq] = p;
            f = fmaf(attn_s[lbi * 32 + m], p, f);
        }
        out_fused[(size_t)cta * 512 + idx] = f;
    }
}

extern "C" void kernel_launch(void* const* d_in, const int* in_sizes, int n_in,
                              void* d_out, int out_size) {
    const float* vert = (const float*)d_in[0];
    const float* horiz = (const float*)d_in[1];
    const unsigned char* mask = (const unsigned char*)d_in[2];
    const float* gw1 = (const float*)d_in[3];
    const float* gb1 = (const float*)d_in[4];
    const float* gw2 = (const float*)d_in[5];
    const float* gb2 = (const float*)d_in[6];
    const float* aw1 = (const float*)d_in[7];
    const float* ab1 = (const float*)d_in[8];
    const float* aw2 = (const float*)d_in[9];
    const float* ab2 = (const float*)d_in[10];

    float* out = (float*)d_out;
    float* out_fused = out;                                   // L*B*D
    float* out_pm = out + (size_t)Lq * Bq * Dq;               // L*B*N*D
    float* out_attn = out_pm + (size_t)Lq * Bq * Nq * Dq;     // B*L*N

    prep_kernel<<<(GHq * KC + 255) / 256, 256>>>(gw1, aw1, mask);

    cudaFuncSetAttribute(fusion_main, cudaFuncAttributeMaxDynamicSharedMemorySize, SMEM_TOTAL);
    fusion_main<<<Lq * Bq / 2, THREADS, SMEM_TOTAL>>>(vert, horiz, mask,
                                                      gb1, gw2, gb2, ab1, aw2, ab2,
                                                      out_fused, out_pm, out_attn);
}

// round 13
// speedup vs baseline: 1.5842x; 1.5842x over previous
#include <cuda_runtime.h>
#include <cuda_fp16.h>
#include <cstdint>
#include <math.h>
#include <float.h>

#define Lq 512
#define Bq 8
#define Nq 32
#define Dq 256
#define GHq 128
#define AHq 64
#define KC 512
#define THREADS 256

// fp16 weights, [n][k] k-contiguous
__device__ __half g_w1h[GHq * KC];     // [128][512]
__device__ __half g_w2h[AHq * Dq];     // [64][256]
__device__ int g_mask_mode;            // 0 = byte bool, 1 = int32, 2 = float32

__global__ void prep_kernel(const float* __restrict__ gw1, const float* __restrict__ aw1,
                            const unsigned char* __restrict__ mask_raw) {
    int i = blockIdx.x * blockDim.x + threadIdx.x;
    if (i < GHq * KC) g_w1h[i] = __float2half_rn(gw1[i]);
    if (i < AHq * Dq) g_w2h[i] = __float2half_rn(aw1[i]);
    // parallel mask-dtype sniffer (block 0): float32 1.0f = {00,00,80,3F};
    // int32 0/1 has zero bytes at j%4!=0; byte-bool has 0/1 bytes everywhere.
    if (blockIdx.x == 0) {
        __shared__ int s_flags[2];
        if (threadIdx.x == 0) { s_flags[0] = 0; s_flags[1] = 0; }
        __syncthreads();
        bool fsig = false, onz = false;
        for (int j = threadIdx.x; j < 4096; j += 256) {
            unsigned char c = mask_raw[j];
            if (j & 3) {
                if (c == 0x3Fu || c == 0x80u) fsig = true;
                if (c != 0) onz = true;
            }
        }
        if (__any_sync(0xffffffffu, fsig) && (threadIdx.x & 31) == 0) atomicOr(&s_flags[0], 1);
        if (__any_sync(0xffffffffu, onz) && (threadIdx.x & 31) == 0) atomicOr(&s_flags[1], 1);
        __syncthreads();
        if (threadIdx.x == 0)
            g_mask_mode = s_flags[0] ? 2 : (s_flags[1] ? 0 : 1);
    }
}

__device__ __forceinline__ uint32_t smem_u32(const void* p) {
    return (uint32_t)__cvta_generic_to_shared(p);
}
__device__ __forceinline__ void ldmatrix_x4(uint32_t* r, uint32_t addr) {
    asm volatile("ldmatrix.sync.aligned.m8n8.x4.shared.b16 {%0,%1,%2,%3}, [%4];"
                 : "=r"(r[0]), "=r"(r[1]), "=r"(r[2]), "=r"(r[3]) : "r"(addr));
}
__device__ __forceinline__ void mma16816(float* c, const uint32_t* a, uint32_t b0, uint32_t b1) {
    asm volatile("mma.sync.aligned.m16n8k16.row.col.f32.f16.f16.f32 "
                 "{%0,%1,%2,%3},{%4,%5,%6,%7},{%8,%9},{%0,%1,%2,%3};"
                 : "+f"(c[0]), "+f"(c[1]), "+f"(c[2]), "+f"(c[3])
                 : "r"(a[0]), "r"(a[1]), "r"(a[2]), "r"(a[3]), "r"(b0), "r"(b1));
}
__device__ __forceinline__ void cp16(uint32_t dst, const void* src) {
    asm volatile("cp.async.cg.shared.global [%0], [%1], 16;" :: "r"(dst), "l"(src));
}
__device__ __forceinline__ void cp_commit() { asm volatile("cp.async.commit_group;"); }
__device__ __forceinline__ void cp_wait0() { asm volatile("cp.async.wait_group 0;" ::: "memory"); }

// SMEM layout (bytes); stride 72 halves = 144 B rows (16B-aligned, conflict-free ldmatrix)
#define A_STRIDE 72
#define SLOT_H 4608                     // halves per A16 slot ([64][72])
#define OFF_A16 0                       // 8 slots x 9216 B = 73728 (V:0-3, H:4-7) — persists for tail
#define OFF_W1 73728                    // [128][72] fp16 = 18432
#define OFF_W2 92160                    // [64][72] fp16 = 9216
#define OFF_GPART 101376                // float [64][4]
#define OFF_GATE (OFF_GPART + 1024)     // float [64]
#define OFF_ATTN (OFF_GATE + 256)       // float [64]
#define SMEM_TOTAL (OFF_ATTN + 256 + 64)

__global__ __launch_bounds__(THREADS, 2)
void fusion_main(const float* __restrict__ vert, const float* __restrict__ horiz,
                 const unsigned char* __restrict__ mask,
                 const float* __restrict__ gb1, const float* __restrict__ gw2,
                 const float* __restrict__ gb2,
                 const float* __restrict__ ab1, const float* __restrict__ aw2,
                 const float* __restrict__ ab2,
                 float* __restrict__ out_fused, float* __restrict__ out_pm,
                 float* __restrict__ out_attn) {
    extern __shared__ char smem[];
    __half* A16 = (__half*)(smem + OFF_A16);
    float* gpart = (float*)(smem + OFF_GPART);
    float* gate_s = (float*)(smem + OFF_GATE);
    float* attn_s = (float*)(smem + OFF_ATTN);

    const int tid = threadIdx.x;
    const int wid = tid >> 5;
    const int lane = tid & 31;
    const int cta = blockIdx.x;          // 2 lb pairs: lb = cta*2 + lbi
    const uint32_t sbase = smem_u32(smem);

    const int mg = wid >> 2;             // warp grid 2m x 4n
    const int ng = wid & 3;

    const int lgrp = lane >> 3;
    const int lrow = (lane & 7) + (lgrp & 1) * 8;
    const int lcol = (lgrp >> 1) * 8;
    const int bn_off = ((lane >> 4) & 1) * 8 + (lane & 7);
    const int bk_off = ((lane >> 3) & 1) * 8;

    // ========== GEMM1 + fused GEMM2 (Yv/Yh) over 8 k64 chunks ==========
    float acc1[2][4][4];
    float accv[2][2][4], acch[2][2][4];
#pragma unroll
    for (int a = 0; a < 2; a++) {
#pragma unroll
        for (int b = 0; b < 4; b++)
#pragma unroll
            for (int c = 0; c < 4; c++) acc1[a][b][c] = 0.f;
#pragma unroll
        for (int b = 0; b < 2; b++)
#pragma unroll
            for (int c = 0; c < 4; c++) { accv[a][b][c] = 0.f; acch[a][b][c] = 0.f; }
    }

#pragma unroll 1
    for (int chunk = 0; chunk < 8; chunk++) {
        const float* feat = (chunk < 4) ? vert : horiz;
        const int kb = (chunk & 3) * 64;
        __syncthreads();                 // W buffers reusable (mma(chunk-1) done)
        // W1 + W2 chunk via cp.async (flies under the A LDG+convert below)
#pragma unroll
        for (int t = 0; t < 4; t++) {
            int j = tid + t * THREADS;   // 128 n x 8 q
            int n = j >> 3;
            int q = j & 7;
            cp16(sbase + OFF_W1 + n * 144 + q * 16,
                 g_w1h + n * KC + chunk * 64 + q * 8);
        }
#pragma unroll
        for (int t = 0; t < 2; t++) {
            int j = tid + t * THREADS;   // 64 n x 8 q
            int n = j >> 3;
            int q = j & 7;
            cp16(sbase + OFF_W2 + n * 144 + q * 16,
                 g_w2h + n * Dq + kb + q * 8);
        }
        cp_commit();
        // stage A chunk into its persistent slot: 64 m x 64 k fp32 -> fp16
        {
            __half* slot = A16 + chunk * SLOT_H;
            const float4* src = (const float4*)(feat + (size_t)cta * 64 * Dq);
#pragma unroll
            for (int t = 0; t < 4; t++) {
                int j = tid + t * THREADS;   // 0..1023
                int m = j >> 4;
                int kq = (j & 15) * 4;
                float4 v = src[m * (Dq / 4) + (kb + kq) / 4];
                __half2 h01 = __floats2half2_rn(v.x, v.y);
                __half2 h23 = __floats2half2_rn(v.z, v.w);
                *(uint2*)&slot[m * A_STRIDE + kq] =
                    make_uint2(*(uint32_t*)&h01, *(uint32_t*)&h23);
            }
        }
        cp_wait0();
        __syncthreads();

        const uint32_t slot_base = sbase + OFF_A16 + chunk * 9216;
#pragma unroll
        for (int ks = 0; ks < 4; ks++) {
            const int kk = ks * 16;
            uint32_t a[2][4];
#pragma unroll
            for (int mt = 0; mt < 2; mt++) {
                int row = mg * 32 + mt * 16 + lrow;
                ldmatrix_x4(a[mt], slot_base + row * 144 + (kk + lcol) * 2);
            }
            // GEMM1
#pragma unroll
            for (int nh = 0; nh < 2; nh++) {
                uint32_t b[4];
                ldmatrix_x4(b, sbase + OFF_W1 +
                               (ng * 32 + nh * 16 + bn_off) * 144 + (kk + bk_off) * 2);
#pragma unroll
                for (int nf2 = 0; nf2 < 2; nf2++) {
                    int nf = nh * 2 + nf2;
#pragma unroll
                    for (int mt = 0; mt < 2; mt++)
                        mma16816(acc1[mt][nf], a[mt], b[nf2 * 2], b[nf2 * 2 + 1]);
                }
            }
            // fused GEMM2 (A frags reused)
            {
                uint32_t b2[4];
                ldmatrix_x4(b2, sbase + OFF_W2 +
                                (ng * 16 + bn_off) * 144 + (kk + bk_off) * 2);
                if (chunk < 4) {
#pragma unroll
                    for (int nf = 0; nf < 2; nf++)
#pragma unroll
                        for (int mt = 0; mt < 2; mt++)
                            mma16816(accv[mt][nf], a[mt], b2[nf * 2], b2[nf * 2 + 1]);
                } else {
#pragma unroll
                    for (int nf = 0; nf < 2; nf++)
#pragma unroll
                        for (int mt = 0; mt < 2; mt++)
                            mma16816(acch[mt][nf], a[mt], b2[nf * 2], b2[nf * 2 + 1]);
                }
            }
        }
    }

    // ---- gate epilogue: relu(C1+gb1) . gw2 -> sigmoid ----
    {
        float p0[2] = {0.f, 0.f}, p1[2] = {0.f, 0.f};
#pragma unroll
        for (int nf = 0; nf < 4; nf++) {
#pragma unroll
            for (int j = 0; j < 2; j++) {
                int n = ng * 32 + nf * 8 + 2 * (lane & 3) + j;
                float b1v = __ldg(&gb1[n]);
                float w2v = __ldg(&gw2[n]);
#pragma unroll
                for (int mt = 0; mt < 2; mt++) {
                    p0[mt] += fmaxf(acc1[mt][nf][j] + b1v, 0.f) * w2v;
                    p1[mt] += fmaxf(acc1[mt][nf][j + 2] + b1v, 0.f) * w2v;
                }
            }
        }
#pragma unroll
        for (int o = 1; o <= 2; o <<= 1) {
#pragma unroll
            for (int mt = 0; mt < 2; mt++) {
                p0[mt] += __shfl_xor_sync(0xffffffffu, p0[mt], o);
                p1[mt] += __shfl_xor_sync(0xffffffffu, p1[mt], o);
            }
        }
        if ((lane & 3) == 0) {
            int r = lane >> 2;
#pragma unroll
            for (int mt = 0; mt < 2; mt++) {
                gpart[(mg * 32 + mt * 16 + r) * 4 + ng] = p0[mt];
                gpart[(mg * 32 + mt * 16 + 8 + r) * 4 + ng] = p1[mt];
            }
        }
        __syncthreads();
        if (tid < 64) {
            float s = gpart[tid * 4] + gpart[tid * 4 + 1] + gpart[tid * 4 + 2] + gpart[tid * 4 + 3];
            s += __ldg(gb2);
            gate_s[tid] = 1.f / (1.f + __expf(-s));
        }
        __syncthreads();
    }

    // ---- logits epilogue: tanh(g*Yv + (1-g)*Yh + ab1) . aw2 ----
    {
        float p0[2] = {0.f, 0.f}, p1[2] = {0.f, 0.f};
        int r = lane >> 2;
        float gA[2], gB[2];
#pragma unroll
        for (int mt = 0; mt < 2; mt++) {
            gA[mt] = gate_s[mg * 32 + mt * 16 + r];
            gB[mt] = gate_s[mg * 32 + mt * 16 + 8 + r];
        }
#pragma unroll
        for (int nf = 0; nf < 2; nf++) {
#pragma unroll
            for (int j = 0; j < 2; j++) {
                int n = ng * 16 + nf * 8 + 2 * (lane & 3) + j;
                float b1v = __ldg(&ab1[n]);
                float w2v = __ldg(&aw2[n]);
#pragma unroll
                for (int mt = 0; mt < 2; mt++) {
                    float pre0 = fmaf(gA[mt], accv[mt][nf][j] - acch[mt][nf][j], acch[mt][nf][j]) + b1v;
                    p0[mt] += tanhf(pre0) * w2v;
                    float pre1 = fmaf(gB[mt], accv[mt][nf][j + 2] - acch[mt][nf][j + 2], acch[mt][nf][j + 2]) + b1v;
                    p1[mt] += tanhf(pre1) * w2v;
                }
            }
        }
#pragma unroll
        for (int o = 1; o <= 2; o <<= 1) {
#pragma unroll
            for (int mt = 0; mt < 2; mt++) {
                p0[mt] += __shfl_xor_sync(0xffffffffu, p0[mt], o);
                p1[mt] += __shfl_xor_sync(0xffffffffu, p1[mt], o);
            }
        }
        if ((lane & 3) == 0) {
#pragma unroll
            for (int mt = 0; mt < 2; mt++) {
                gpart[(mg * 32 + mt * 16 + r) * 4 + ng] = p0[mt];
                gpart[(mg * 32 + mt * 16 + 8 + r) * 4 + ng] = p1[mt];
            }
        }
        __syncthreads();
    }

    // ---- masked softmax per lb (2 warps; lane = msg) ----
    if (tid < 64) {
        int lbi = tid >> 5;
        int msg = tid & 31;
        int lb = cta * 2 + lbi;
        int l = lb >> 3, b = lb & 7;
        float lg = gpart[tid * 4] + gpart[tid * 4 + 1] + gpart[tid * 4 + 2] + gpart[tid * 4 + 3];
        lg += __ldg(ab2);
        size_t midx = ((size_t)b * Nq + msg) * Lq + l;
        int mode = g_mask_mode;
        bool valid;
        if (mode == 2)      valid = ((const float*)mask)[midx] != 0.0f;
        else if (mode == 1) valid = ((const int*)mask)[midx] != 0;
        else                valid = mask[midx] != 0;
        float mv = valid ? lg : -FLT_MAX;
#pragma unroll
        for (int o = 16; o >= 1; o >>= 1)
            mv = fmaxf(mv, __shfl_xor_sync(0xffffffffu, mv, o));
        float e = valid ? __expf(lg - mv) : 0.f;
        float s = e;
#pragma unroll
        for (int o = 16; o >= 1; o >>= 1)
            s += __shfl_xor_sync(0xffffffffu, s, o);
        float a = (s > 0.f) ? e / s : 0.f;
        attn_s[tid] = a;
        out_attn[((size_t)b * Lq + l) * Nq + msg] = a;
    }
    __syncthreads();

    // ---- blend + fused from SMEM fp16 (no gmem re-read): p = g*(v-h)+h ----
#pragma unroll 1
    for (int it = 0; it < 2; it++) {
        int idx = tid + it * THREADS;    // 0..511 = 2 lb x 256 d
        int lbi = idx >> 8;
        int d = idx & 255;
        const __half* vslot = A16 + (d >> 6) * SLOT_H + (d & 63);
        const __half* hslot = A16 + (4 + (d >> 6)) * SLOT_H + (d & 63);
        float* pmb = out_pm + (size_t)(cta * 64 + lbi * 32) * Dq + d;
        float f = 0.f;
#pragma unroll
        for (int m = 0; m < Nq; m++) {
            int row = lbi * 32 + m;
            float g = gate_s[row];
            float v = __half2float(vslot[row * A_STRIDE]);
            float h = __half2float(hslot[row * A_STRIDE]);
            float p = fmaf(g, v - h, h);
            pmb[m * Dq] = p;
            f = fmaf(attn_s[row], p, f);
        }
        out_fused[(size_t)cta * 512 + idx] = f;
    }
}

extern "C" void kernel_launch(void* const* d_in, const int* in_sizes, int n_in,
                              void* d_out, int out_size) {
    const float* vert = (const float*)d_in[0];
    const float* horiz = (const float*)d_in[1];
    const unsigned char* mask = (const unsigned char*)d_in[2];
    const float* gw1 = (const float*)d_in[3];
    const float* gb1 = (const float*)d_in[4];
    const float* gw2 = (const float*)d_in[5];
    const float* gb2 = (const float*)d_in[6];
    const float* aw1 = (const float*)d_in[7];
    const float* ab1 = (const float*)d_in[8];
    const float* aw2 = (const float*)d_in[9];
    const float* ab2 = (const float*)d_in[10];

    float* out = (float*)d_out;
    float* out_fused = out;                                   // L*B*D
    float* out_pm = out + (size_t)Lq * Bq * Dq;               // L*B*N*D
    float* out_attn = out_pm + (size_t)Lq * Bq * Nq * Dq;     // B*L*N

    prep_kernel<<<(GHq * KC + 255) / 256, 256>>>(gw1, aw1, mask);

    cudaFuncSetAttribute(fusion_main, cudaFuncAttributeMaxDynamicSharedMemorySize, SMEM_TOTAL);
    fusion_main<<<Lq * Bq / 2, THREADS, SMEM_TOTAL>>>(vert, horiz, mask,
                                                      gb1, gw2, gb2, ab1, aw2, ab2,
                                                      out_fused, out_pm, out_attn);
}